// round 1
// baseline (speedup 1.0000x reference)
#include <cuda_runtime.h>

#define DEVINL static __device__ __forceinline__

// ===================== compile-time int-list machinery =====================
template<int... Is> struct IL { static constexpr int size = sizeof...(Is); };

template<int H, typename L> struct Prepend;
template<int H, int... Is> struct Prepend<H, IL<Is...>> { using type = IL<H, Is...>; };

template<typename A, typename B> struct Concat;
template<int... As, int... Bs> struct Concat<IL<As...>, IL<Bs...>> { using type = IL<As..., Bs...>; };

template<int I, typename L> struct Get;
template<int H, int... T> struct Get<0, IL<H, T...>> { static constexpr int value = H; };
template<int I, int H, int... T> struct Get<I, IL<H, T...>> { static constexpr int value = Get<I-1, IL<T...>>::value; };

template<int N, typename L> struct Take;
template<> struct Take<0, IL<>> { using type = IL<>; };
template<int H, int... T> struct Take<0, IL<H, T...>> { using type = IL<>; };
template<int N, int H, int... T> struct Take<N, IL<H, T...>> {
  using type = typename Prepend<H, typename Take<N-1, IL<T...>>::type>::type;
};

template<int N, typename L> struct Drop;
template<> struct Drop<0, IL<>> { using type = IL<>; };
template<int H, int... T> struct Drop<0, IL<H, T...>> { using type = IL<H, T...>; };
template<int N, int H, int... T> struct Drop<N, IL<H, T...>> { using type = typename Drop<N-1, IL<T...>>::type; };

template<typename L> struct EvenOdd;
template<> struct EvenOdd<IL<>> { using even = IL<>; using odd = IL<>; };
template<int A> struct EvenOdd<IL<A>> { using even = IL<A>; using odd = IL<>; };
template<int A, int Bv, int... R> struct EvenOdd<IL<A, Bv, R...>> {
  using even = typename Prepend<A,  typename EvenOdd<IL<R...>>::even>::type;
  using odd  = typename Prepend<Bv, typename EvenOdd<IL<R...>>::odd >::type;
};

// Interleave E0,O0,E1,O1,... (E is always >= O in length here)
template<typename E, typename O> struct Interleave;
template<typename E> struct Interleave<E, IL<>> { using type = E; };
template<int E0, int... Es, int O0, int... Os>
struct Interleave<IL<E0, Es...>, IL<O0, Os...>> {
  using type = typename Concat<IL<E0, O0>, typename Interleave<IL<Es...>, IL<Os...>>::type>::type;
};

// ===================== compare-exchange =====================
DEVINL void cas_(float& x, float& y) {
  float lo = fminf(x, y);
  float hi = fmaxf(x, y);
  x = lo; y = hi;
}

// cleanup step of odd-even merge: cas(O[i], E[i+1])
template<typename E, typename O> struct Cleanup {
  DEVINL void run(float*) {}
};
template<int E0, int E1, int... Es, int O0, int... Os>
struct Cleanup<IL<E0, E1, Es...>, IL<O0, Os...>> {
  DEVINL void run(float* v) {
    cas_(v[O0], v[E1]);
    Cleanup<IL<E1, Es...>, IL<Os...>>::run(v);
  }
};

// ===================== generalized Batcher odd-even merge =====================
// Merges two sorted slot-lists (in-place on register array), `type` = slot order
// of the sorted result.
template<typename A, typename B, int M = A::size, int N = B::size>
struct Merge {
  using ME = Merge<typename EvenOdd<A>::even, typename EvenOdd<B>::even>;
  using MO = Merge<typename EvenOdd<A>::odd,  typename EvenOdd<B>::odd >;
  using E = typename ME::type;
  using O = typename MO::type;
  using type = typename Interleave<E, O>::type;
  DEVINL void run(float* v) { ME::run(v); MO::run(v); Cleanup<E, O>::run(v); }
};
template<typename A, typename B, int N> struct Merge<A, B, 0, N> { using type = B; DEVINL void run(float*) {} };
template<typename A, typename B, int M> struct Merge<A, B, M, 0> { using type = A; DEVINL void run(float*) {} };
template<typename A, typename B>        struct Merge<A, B, 0, 0> { using type = IL<>; DEVINL void run(float*) {} };
template<typename A, typename B> struct Merge<A, B, 1, 1> {
  static constexpr int a0 = Get<0, A>::value;
  static constexpr int b0 = Get<0, B>::value;
  using type = IL<a0, b0>;
  DEVINL void run(float* v) { cas_(v[a0], v[b0]); }
};

// odd-even merge sort
template<typename L, int N = L::size>
struct Sort {
  static constexpr int Half = N / 2;
  using SA = Sort<typename Take<Half, L>::type>;
  using SB = Sort<typename Drop<Half, L>::type>;
  using MG = Merge<typename SA::type, typename SB::type>;
  using type = typename MG::type;
  DEVINL void run(float* v) { SA::run(v); SB::run(v); MG::run(v); }
};
template<typename L> struct Sort<L, 0> { using type = IL<>; DEVINL void run(float*) {} };
template<typename L> struct Sort<L, 1> { using type = L;    DEVINL void run(float*) {} };

template<int S, int N> struct Range {
  using type = typename Prepend<S, typename Range<S+1, N-1>::type>::type;
};
template<int S> struct Range<S, 0> { using type = IL<>; };

// Rank-26 (0-indexed) of union of sorted A(25) and sorted B(24):
//   s_r = max_{i+j=r} min(A[i], B[j])  with OOB -> +inf.
// Fold over i = 3..24 (j = 26-i in [2..23]); A[2] and B[1] handled by caller.
template<int I, int IEnd, typename A, typename B> struct SelFold {
  DEVINL float run(const float* v) {
    float t = fminf(v[Get<I, A>::value], v[Get<26 - I, B>::value]);
    return fmaxf(t, SelFold<I + 1, IEnd, A, B>::run(v));
  }
};
template<int IEnd, typename A, typename B> struct SelFold<IEnd, IEnd, A, B> {
  DEVINL float run(const float* v) {
    return fminf(v[Get<IEnd, A>::value], v[Get<26 - IEnd, B>::value]);
  }
};

// ===================== problem constants =====================
constexpr int Bn = 4, Hn = 256, Wn = 256, Cn = 16;
constexpr int TX = 4, TY = 4;              // output pixels per block
constexpr int TW = TX + 6, TH = TY + 6;    // 10 x 10 haloed tile
constexpr int NTHREADS = TX * TY * Cn;     // 256

// Slot layout of V[49]: 0..8 inner 3x3, 9..24 ring of 5x5, 25..48 ring of 7x7
using L9  = Range<0, 9>::type;
using L16 = Range<9, 16>::type;
using L24 = Range<25, 24>::type;
using S9  = Sort<L9>;
using S16 = Sort<L16>;
using S24 = Sort<L24>;
using M25 = Merge<S9::type, S16::type>;   // sorted 25 = inner9 ∪ ring16

__global__ void __launch_bounds__(NTHREADS)
amblock_kernel(const float* __restrict__ x, const float* __restrict__ w,
               float* __restrict__ out) {
  __shared__ float tile[TH * TW * Cn];   // 1600 floats
  __shared__ float wsm[48 * 16];         // 768 floats
  __shared__ float feat[TX * TY * 49];   // 16 pixels x 48 (stride 49 vs bank conflicts)

  const int tid = threadIdx.x;
  const int bx = blockIdx.x, by = blockIdx.y, bz = blockIdx.z;

  // weights -> smem
  for (int i = tid; i < 48 * 16; i += NTHREADS) wsm[i] = w[i];

  // haloed input tile -> smem (zero padding outside the image)
  const int y0 = by * TY - 3, x0 = bx * TX - 3;
  for (int i = tid; i < TH * TW * Cn; i += NTHREADS) {
    int c  = i & (Cn - 1);
    int p  = i >> 4;
    int py = p / TW, px = p - py * TW;
    int gy = y0 + py, gx = x0 + px;
    float v = 0.f;
    if ((unsigned)gy < (unsigned)Hn && (unsigned)gx < (unsigned)Wn)
      v = x[(((bz * Hn + gy) * Wn) + gx) * Cn + c];
    tile[i] = v;
  }
  __syncthreads();

  {
    const int c   = tid & 15;
    const int pix = tid >> 4;
    const int py  = pix >> 2;      // TX = 4
    const int px  = pix & 3;
    const float* base = &tile[((py + 3) * TW + (px + 3)) * Cn + c];

    float V[49];
    // inner 3x3 -> slots 0..8
#pragma unroll
    for (int dy = -1; dy <= 1; dy++)
#pragma unroll
      for (int dx = -1; dx <= 1; dx++)
        V[(dy + 1) * 3 + (dx + 1)] = base[(dy * TW + dx) * Cn];
    // 5x5 ring -> slots 9..24
    {
      int k = 9;
#pragma unroll
      for (int dy = -2; dy <= 2; dy++)
#pragma unroll
        for (int dx = -2; dx <= 2; dx++)
          if (dy < -1 || dy > 1 || dx < -1 || dx > 1) { V[k] = base[(dy * TW + dx) * Cn]; k++; }
    }
    // 7x7 ring -> slots 25..48
    {
      int k = 25;
#pragma unroll
      for (int dy = -3; dy <= 3; dy++)
#pragma unroll
        for (int dx = -3; dx <= 3; dx++)
          if (dy < -2 || dy > 2 || dx < -2 || dx > 2) { V[k] = base[(dy * TW + dx) * Cn]; k++; }
    }

    // k=3: ascending index 6 of sorted 9
    S9::run(V);
    const float m3 = V[Get<6, S9::type>::value];

    // k=5: ascending index 14 of sorted 25 (merge inner9 with ring16)
    S16::run(V);
    M25::run(V);
    const float m5 = V[Get<14, M25::type>::value];

    // k=7: ascending index 26 of union(sorted25, sorted24) via max-min identity
    S24::run(V);
    float m7 = fmaxf(V[Get<2, M25::type>::value], V[Get<1, S24::type>::value]);
    m7 = fmaxf(m7, SelFold<3, 24, M25::type, S24::type>::run(V));

    // concat order from reference: [m7, m3, m5]
    feat[pix * 49 +      c] = m7;
    feat[pix * 49 + 16 + c] = m3;
    feat[pix * 49 + 32 + c] = m5;
  }
  __syncthreads();

  // fused 1x1 conv: out[pix][o] = sum_c feat[pix][c] * w[c][o]
  {
    const int o   = tid & 15;
    const int pix = tid >> 4;
    const float* f = &feat[pix * 49];
    float acc = 0.f;
#pragma unroll
    for (int cc = 0; cc < 48; cc++) acc = fmaf(f[cc], wsm[cc * 16 + o], acc);
    const int py = pix >> 2, px = pix & 3;
    const int gy = by * TY + py, gx = bx * TX + px;
    out[(((bz * Hn + gy) * Wn) + gx) * Cn + o] = acc;
  }
}

extern "C" void kernel_launch(void* const* d_in, const int* in_sizes, int n_in,
                              void* d_out, int out_size) {
  const float* x = (const float*)d_in[0];
  const float* w = (const float*)d_in[1];
  float* out = (float*)d_out;
  dim3 grid(Wn / TX, Hn / TY, Bn);
  amblock_kernel<<<grid, NTHREADS>>>(x, w, out);
}

// round 3
// speedup vs baseline: 1.0526x; 1.0526x over previous
#include <cuda_runtime.h>
#include <cstdint>

#define DEVINL static __device__ __forceinline__

// ===================== compile-time int-list machinery =====================
template<int... Is> struct IL { static constexpr int size = sizeof...(Is); };

template<int H, typename L> struct Prepend;
template<int H, int... Is> struct Prepend<H, IL<Is...>> { using type = IL<H, Is...>; };

template<typename A, typename B> struct Concat;
template<int... As, int... Bs> struct Concat<IL<As...>, IL<Bs...>> { using type = IL<As..., Bs...>; };

template<int I, typename L> struct Get;
template<int H, int... T> struct Get<0, IL<H, T...>> { static constexpr int value = H; };
template<int I, int H, int... T> struct Get<I, IL<H, T...>> { static constexpr int value = Get<I-1, IL<T...>>::value; };

template<int N, typename L> struct Take;
template<> struct Take<0, IL<>> { using type = IL<>; };
template<int H, int... T> struct Take<0, IL<H, T...>> { using type = IL<>; };
template<int N, int H, int... T> struct Take<N, IL<H, T...>> {
  using type = typename Prepend<H, typename Take<N-1, IL<T...>>::type>::type;
};

template<int N, typename L> struct Drop;
template<> struct Drop<0, IL<>> { using type = IL<>; };
template<int H, int... T> struct Drop<0, IL<H, T...>> { using type = IL<H, T...>; };
template<int N, int H, int... T> struct Drop<N, IL<H, T...>> { using type = typename Drop<N-1, IL<T...>>::type; };

template<typename L> struct EvenOdd;
template<> struct EvenOdd<IL<>> { using even = IL<>; using odd = IL<>; };
template<int A> struct EvenOdd<IL<A>> { using even = IL<A>; using odd = IL<>; };
template<int A, int Bv, int... R> struct EvenOdd<IL<A, Bv, R...>> {
  using even = typename Prepend<A,  typename EvenOdd<IL<R...>>::even>::type;
  using odd  = typename Prepend<Bv, typename EvenOdd<IL<R...>>::odd >::type;
};

template<typename E, typename O> struct Interleave;
template<typename E> struct Interleave<E, IL<>> { using type = E; };
template<int E0, int... Es, int O0, int... Os>
struct Interleave<IL<E0, Es...>, IL<O0, Os...>> {
  using type = typename Concat<IL<E0, O0>, typename Interleave<IL<Es...>, IL<Os...>>::type>::type;
};

// ===================== compare-exchange variants =====================
// P=0: exact FMNMX pair (alu pipe). P=1: arithmetic form (fma pipe), ~1ulp error.
template<int P> struct CasOp;
template<> struct CasOp<0> {
  DEVINL void apply(float& x, float& y) {
    float lo = fminf(x, y);
    float hi = fmaxf(x, y);
    x = lo; y = hi;
  }
};
template<> struct CasOp<1> {
  DEVINL void apply(float& x, float& y) {
    float d = x - y;
    float s = x + y;
    float mn = (s - fabsf(d)) * 0.5f;   // FADD(|.|) + FMUL -> fma pipe
    float mx = s - mn;                  // FADD
    x = mn; y = mx;
  }
};

// cleanup step of odd-even merge: cas(O[i], E[i+1])
template<int P, typename E, typename O> struct Cleanup {
  DEVINL void run(float*) {}
};
template<int P, int E0, int E1, int... Es, int O0, int... Os>
struct Cleanup<P, IL<E0, E1, Es...>, IL<O0, Os...>> {
  DEVINL void run(float* v) {
    CasOp<P>::apply(v[O0], v[E1]);
    Cleanup<P, IL<E1, Es...>, IL<Os...>>::run(v);
  }
};

// ===================== generalized Batcher odd-even merge =====================
template<int P, typename A, typename B, int M = A::size, int N = B::size>
struct Merge {
  using ME = Merge<P, typename EvenOdd<A>::even, typename EvenOdd<B>::even>;
  using MO = Merge<P, typename EvenOdd<A>::odd,  typename EvenOdd<B>::odd >;
  using E = typename ME::type;
  using O = typename MO::type;
  using type = typename Interleave<E, O>::type;
  DEVINL void run(float* v) { ME::run(v); MO::run(v); Cleanup<P, E, O>::run(v); }
};
template<int P, typename A, typename B, int N> struct Merge<P, A, B, 0, N> { using type = B; DEVINL void run(float*) {} };
template<int P, typename A, typename B, int M> struct Merge<P, A, B, M, 0> { using type = A; DEVINL void run(float*) {} };
template<int P, typename A, typename B>        struct Merge<P, A, B, 0, 0> { using type = IL<>; DEVINL void run(float*) {} };
template<int P, typename A, typename B> struct Merge<P, A, B, 1, 1> {
  static constexpr int a0 = Get<0, A>::value;
  static constexpr int b0 = Get<0, B>::value;
  using type = IL<a0, b0>;
  DEVINL void run(float* v) { CasOp<P>::apply(v[a0], v[b0]); }
};

// odd-even merge sort
template<int P, typename L, int N = L::size>
struct Sort {
  static constexpr int Half = N / 2;
  using SA = Sort<P, typename Take<Half, L>::type>;
  using SB = Sort<P, typename Drop<Half, L>::type>;
  using MG = Merge<P, typename SA::type, typename SB::type>;
  using type = typename MG::type;
  DEVINL void run(float* v) { SA::run(v); SB::run(v); MG::run(v); }
};
template<int P, typename L> struct Sort<P, L, 0> { using type = IL<>; DEVINL void run(float*) {} };
template<int P, typename L> struct Sort<P, L, 1> { using type = L;    DEVINL void run(float*) {} };

template<int S, int N> struct Range {
  using type = typename Prepend<S, typename Range<S+1, N-1>::type>::type;
};
template<int S> struct Range<S, 0> { using type = IL<>; };

// ===================== opaque smem ld/st (defeat reg-forwarding) ==========
DEVINL uint32_t s2u(const void* p) { return (uint32_t)__cvta_generic_to_shared(p); }
DEVINL void sts_f(uint32_t a, float v) {
  asm volatile("st.shared.f32 [%0], %1;" :: "r"(a), "f"(v) : "memory");
}
DEVINL float lds_f(uint32_t a) {
  float v;
  asm volatile("ld.shared.f32 %0, [%1];" : "=f"(v) : "r"(a) : "memory");
  return v;
}

// ===================== problem constants =====================
constexpr int Bn = 4, Hn = 256, Wn = 256, Cn = 16;
constexpr int TX = 4, TY = 4;              // output pixels per block
constexpr int TW = TX + 6, TH = TY + 6;    // 10 x 10 haloed tile
constexpr int NTHREADS = TX * TY * Cn;     // 256
constexpr int NA = 23;                     // staged ranks of sorted25: A[2..24]

// Slot layout of V: 0..8 inner 3x3, 9..24 ring of 5x5, 25..48 ring of 7x7
using L9  = Range<0, 9>::type;
using L16 = Range<9, 16>::type;
using L24 = Range<25, 24>::type;
using S9  = Sort<0, L9>;
using S16 = Sort<1, L16>;                  // arithmetic CAS -> fma pipe
using S24 = Sort<0, L24>;
using M25 = Merge<0, typename S9::type, typename S16::type>;
using A25 = typename M25::type;
using B24 = typename S24::type;

// Stage sorted25 ranks R..24 to smem (values only; no constexpr arrays)
template<int R> struct Stage {
  DEVINL void run(const float* v, uint32_t ab) {
    sts_f(ab + (R - 2) * 4, v[Get<R, A25>::value]);
    Stage<R + 1>::run(v, ab);
  }
};
template<> struct Stage<25> { DEVINL void run(const float*, uint32_t) {} };

// Rank-26 of union(sorted25 A in smem, sorted24 B in regs):
//   fold over i (step 2 per chain): t_i = min(A[i], B[26-i]); acc = max over chain
template<int I, int IEnd> struct Sel {
  DEVINL float run(const float* v, uint32_t ab) {
    float t = fminf(lds_f(ab + (I - 2) * 4), v[Get<26 - I, B24>::value]);
    return fmaxf(t, Sel<I + 2, IEnd>::run(v, ab));
  }
};
template<int IEnd> struct Sel<IEnd, IEnd> {
  DEVINL float run(const float* v, uint32_t ab) {
    return fminf(lds_f(ab + (IEnd - 2) * 4), v[Get<26 - IEnd, B24>::value]);
  }
};

__global__ void __launch_bounds__(NTHREADS, 5)
amblock_kernel(const float* __restrict__ x, const float* __restrict__ w,
               float* __restrict__ out) {
  __shared__ float tile[TH * TW * Cn];     // 1600 floats
  __shared__ float wsm[48 * 16];           // 768 floats
  __shared__ float feat[TX * TY * 49];     // 784 floats
  __shared__ float Ast[NTHREADS * NA];     // 5888 floats (stride 23: odd -> no conflicts)

  const int tid = threadIdx.x;
  const int bx = blockIdx.x, by = blockIdx.y, bz = blockIdx.z;

  for (int i = tid; i < 48 * 16; i += NTHREADS) wsm[i] = w[i];

  const int y0 = by * TY - 3, x0 = bx * TX - 3;
  for (int i = tid; i < TH * TW * Cn; i += NTHREADS) {
    int c  = i & (Cn - 1);
    int p  = i >> 4;
    int py = p / TW, px = p - py * TW;
    int gy = y0 + py, gx = x0 + px;
    float v = 0.f;
    if ((unsigned)gy < (unsigned)Hn && (unsigned)gx < (unsigned)Wn)
      v = x[(((bz * Hn + gy) * Wn) + gx) * Cn + c];
    tile[i] = v;
  }
  __syncthreads();

  const int c   = tid & 15;
  const int pix = tid >> 4;
  {
    const int py  = pix >> 2;
    const int px  = pix & 3;
    const float* base = &tile[((py + 3) * TW + (px + 3)) * Cn + c];
    const uint32_t tb = s2u(base);
    const uint32_t ab = s2u(&Ast[tid * NA]);

    float V[49];
    // inner 3x3 -> slots 0..8
#pragma unroll
    for (int dy = -1; dy <= 1; dy++)
#pragma unroll
      for (int dx = -1; dx <= 1; dx++)
        V[(dy + 1) * 3 + (dx + 1)] = base[(dy * TW + dx) * Cn];
    // 5x5 ring -> slots 9..24
    {
      int k = 9;
#pragma unroll
      for (int dy = -2; dy <= 2; dy++)
#pragma unroll
        for (int dx = -2; dx <= 2; dx++)
          if (dy < -1 || dy > 1 || dx < -1 || dx > 1) { V[k] = base[(dy * TW + dx) * Cn]; k++; }
    }

    // k=3: ascending index 6 of sorted 9
    S9::run(V);
    const float m3 = V[Get<6, typename S9::type>::value];

    // k=5: ascending index 14 of sorted 25 (merge inner9 with ring16)
    S16::run(V);
    M25::run(V);
    const float m5 = V[Get<14, A25>::value];

    // Stage sorted25 ranks 2..24 to smem (opaque stores -> registers die here)
    Stage<2>::run(V, ab);

    // 7x7 ring -> slots 25..48 (opaque LDS: cannot be hoisted above staging)
    {
      int k = 25;
#pragma unroll
      for (int dy = -3; dy <= 3; dy++)
#pragma unroll
        for (int dx = -3; dx <= 3; dx++)
          if (dy < -2 || dy > 2 || dx < -2 || dx > 2) { V[k] = lds_f(tb + (dy * TW + dx) * 64); k++; }
    }

    S24::run(V);

    // k=7: rank 26 of union: m7 = max(A[2], B[1], max_{i=3..24} min(A[i], B[26-i]))
    float acc0 = fmaxf(lds_f(ab + 0), V[Get<1, B24>::value]);
    acc0 = fmaxf(acc0, Sel<4, 24>::run(V, ab));   // even i chain
    float acc1 = Sel<3, 23>::run(V, ab);          // odd i chain
    const float m7 = fmaxf(acc0, acc1);

    // concat order from reference: [m7, m3, m5]
    feat[pix * 49 +      c] = m7;
    feat[pix * 49 + 16 + c] = m3;
    feat[pix * 49 + 32 + c] = m5;
  }
  __syncthreads();

  // fused 1x1 conv: out[pix][o] = sum_c feat[pix][c] * w[c][o]
  {
    const int o = c;
    const float* f = &feat[pix * 49];
    float acc = 0.f;
#pragma unroll
    for (int cc = 0; cc < 48; cc++) acc = fmaf(f[cc], wsm[cc * 16 + o], acc);
    const int py = pix >> 2, px = pix & 3;
    const int gy = by * TY + py, gx = bx * TX + px;
    out[(((bz * Hn + gy) * Wn) + gx) * Cn + o] = acc;
  }
}

extern "C" void kernel_launch(void* const* d_in, const int* in_sizes, int n_in,
                              void* d_out, int out_size) {
  const float* x = (const float*)d_in[0];
  const float* w = (const float*)d_in[1];
  float* out = (float*)d_out;
  dim3 grid(Wn / TX, Hn / TY, Bn);
  amblock_kernel<<<grid, NTHREADS>>>(x, w, out);
}

// round 4
// speedup vs baseline: 1.8593x; 1.7664x over previous
#include <cuda_runtime.h>
#include <cuda_fp16.h>
#include <cstdint>

#define DEVINL static __device__ __forceinline__

// ===================== compile-time int-list machinery =====================
template<int... Is> struct IL { static constexpr int size = sizeof...(Is); };

template<int H, typename L> struct Prepend;
template<int H, int... Is> struct Prepend<H, IL<Is...>> { using type = IL<H, Is...>; };

template<typename A, typename B> struct Concat;
template<int... As, int... Bs> struct Concat<IL<As...>, IL<Bs...>> { using type = IL<As..., Bs...>; };

template<int I, typename L> struct Get;
template<int H, int... T> struct Get<0, IL<H, T...>> { static constexpr int value = H; };
template<int I, int H, int... T> struct Get<I, IL<H, T...>> { static constexpr int value = Get<I-1, IL<T...>>::value; };

template<int N, typename L> struct Take;
template<> struct Take<0, IL<>> { using type = IL<>; };
template<int H, int... T> struct Take<0, IL<H, T...>> { using type = IL<>; };
template<int N, int H, int... T> struct Take<N, IL<H, T...>> {
  using type = typename Prepend<H, typename Take<N-1, IL<T...>>::type>::type;
};

template<int N, typename L> struct Drop;
template<> struct Drop<0, IL<>> { using type = IL<>; };
template<int H, int... T> struct Drop<0, IL<H, T...>> { using type = IL<H, T...>; };
template<int N, int H, int... T> struct Drop<N, IL<H, T...>> { using type = typename Drop<N-1, IL<T...>>::type; };

template<typename L> struct EvenOdd;
template<> struct EvenOdd<IL<>> { using even = IL<>; using odd = IL<>; };
template<int A> struct EvenOdd<IL<A>> { using even = IL<A>; using odd = IL<>; };
template<int A, int Bv, int... R> struct EvenOdd<IL<A, Bv, R...>> {
  using even = typename Prepend<A,  typename EvenOdd<IL<R...>>::even>::type;
  using odd  = typename Prepend<Bv, typename EvenOdd<IL<R...>>::odd >::type;
};

template<typename E, typename O> struct Interleave;
template<typename E> struct Interleave<E, IL<>> { using type = E; };
template<int E0, int... Es, int O0, int... Os>
struct Interleave<IL<E0, Es...>, IL<O0, Os...>> {
  using type = typename Concat<IL<E0, O0>, typename Interleave<IL<Es...>, IL<Os...>>::type>::type;
};

// ===================== packed f16x2 compare-exchange =====================
DEVINL void cas_(__half2& x, __half2& y) {
  __half2 lo = __hmin2(x, y);
  __half2 hi = __hmax2(x, y);
  x = lo; y = hi;
}

// cleanup step of odd-even merge: cas(O[i], E[i+1])
template<typename E, typename O> struct Cleanup {
  DEVINL void run(__half2*) {}
};
template<int E0, int E1, int... Es, int O0, int... Os>
struct Cleanup<IL<E0, E1, Es...>, IL<O0, Os...>> {
  DEVINL void run(__half2* v) {
    cas_(v[O0], v[E1]);
    Cleanup<IL<E1, Es...>, IL<Os...>>::run(v);
  }
};

// ===================== generalized Batcher odd-even merge =====================
template<typename A, typename B, int M = A::size, int N = B::size>
struct Merge {
  using ME = Merge<typename EvenOdd<A>::even, typename EvenOdd<B>::even>;
  using MO = Merge<typename EvenOdd<A>::odd,  typename EvenOdd<B>::odd >;
  using E = typename ME::type;
  using O = typename MO::type;
  using type = typename Interleave<E, O>::type;
  DEVINL void run(__half2* v) { ME::run(v); MO::run(v); Cleanup<E, O>::run(v); }
};
template<typename A, typename B, int N> struct Merge<A, B, 0, N> { using type = B; DEVINL void run(__half2*) {} };
template<typename A, typename B, int M> struct Merge<A, B, M, 0> { using type = A; DEVINL void run(__half2*) {} };
template<typename A, typename B>        struct Merge<A, B, 0, 0> { using type = IL<>; DEVINL void run(__half2*) {} };
template<typename A, typename B> struct Merge<A, B, 1, 1> {
  static constexpr int a0 = Get<0, A>::value;
  static constexpr int b0 = Get<0, B>::value;
  using type = IL<a0, b0>;
  DEVINL void run(__half2* v) { cas_(v[a0], v[b0]); }
};

// odd-even merge sort
template<typename L, int N = L::size>
struct Sort {
  static constexpr int Half = N / 2;
  using SA = Sort<typename Take<Half, L>::type>;
  using SB = Sort<typename Drop<Half, L>::type>;
  using MG = Merge<typename SA::type, typename SB::type>;
  using type = typename MG::type;
  DEVINL void run(__half2* v) { SA::run(v); SB::run(v); MG::run(v); }
};
template<typename L> struct Sort<L, 0> { using type = IL<>; DEVINL void run(__half2*) {} };
template<typename L> struct Sort<L, 1> { using type = L;    DEVINL void run(__half2*) {} };

template<int S, int N> struct Range {
  using type = typename Prepend<S, typename Range<S+1, N-1>::type>::type;
};
template<int S> struct Range<S, 0> { using type = IL<>; };

// ===================== opaque smem ld/st + bit casts =====================
DEVINL uint32_t s2u(const void* p) { return (uint32_t)__cvta_generic_to_shared(p); }
DEVINL void sts_u(uint32_t a, uint32_t v) {
  asm volatile("st.shared.b32 [%0], %1;" :: "r"(a), "r"(v) : "memory");
}
DEVINL uint32_t lds_u(uint32_t a) {
  uint32_t v;
  asm volatile("ld.shared.b32 %0, [%1];" : "=r"(v) : "r"(a) : "memory");
  return v;
}
DEVINL uint32_t h2u(__half2 h) { return *reinterpret_cast<uint32_t*>(&h); }
DEVINL __half2 u2h(uint32_t u) { return *reinterpret_cast<__half2*>(&u); }

// ===================== problem constants =====================
constexpr int Bn = 4, Hn = 256, Wn = 256, Cn = 16;
constexpr int TX = 8, TY = 4;              // output pixels per block: 32
constexpr int TW = TX + 6, TH = TY + 6;    // 14 x 10 haloed tile
constexpr int NPIX = TX * TY;              // 32
constexpr int NPR  = Cn / 2;               // 8 channel-pairs
constexpr int NTHREADS = NPIX * NPR;       // 256
constexpr int NA = 23;                     // staged ranks of sorted25: A[2..24]

// Slot layout of V: 0..8 inner 3x3, 9..24 ring of 5x5, 25..48 ring of 7x7
using L9  = Range<0, 9>::type;
using L16 = Range<9, 16>::type;
using L24 = Range<25, 24>::type;
using S9  = Sort<L9>;
using S16 = Sort<L16>;
using S24 = Sort<L24>;
using M25 = Merge<typename S9::type, typename S16::type>;
using A25 = typename M25::type;
using B24 = typename S24::type;

// Stage sorted25 ranks R..24 to smem (opaque stores kill register liveness)
template<int R> struct Stage {
  DEVINL void run(const __half2* v, uint32_t ab) {
    sts_u(ab + (R - 2) * 4, h2u(v[Get<R, A25>::value]));
    Stage<R + 1>::run(v, ab);
  }
};
template<> struct Stage<25> { DEVINL void run(const __half2*, uint32_t) {} };

// Rank-26 of union(sorted25 A in smem, sorted24 B in regs), per f16 lane:
//   chain over i step 2: t = min(A[i], B[26-i]); acc = max(acc, t)
template<int I, int IEnd> struct Sel {
  DEVINL __half2 run(const __half2* v, uint32_t ab) {
    __half2 t = __hmin2(u2h(lds_u(ab + (I - 2) * 4)), v[Get<26 - I, B24>::value]);
    return __hmax2(t, Sel<I + 2, IEnd>::run(v, ab));
  }
};
template<int IEnd> struct Sel<IEnd, IEnd> {
  DEVINL __half2 run(const __half2* v, uint32_t ab) {
    return __hmin2(u2h(lds_u(ab + (IEnd - 2) * 4)), v[Get<26 - IEnd, B24>::value]);
  }
};

__global__ void __launch_bounds__(NTHREADS, 6)
amblock_kernel(const float* __restrict__ x, const float* __restrict__ w,
               float* __restrict__ out) {
  __shared__ uint32_t tile[TH * TW * NPR];   // half2 tile: 1120 words (4.4KB)
  __shared__ float wsm[48 * 16];             // 3KB
  __shared__ float feat[NPIX * 49];          // 6.3KB
  __shared__ uint32_t Ast[NTHREADS * NA];    // 23KB (stride 23 -> conflict-free)

  const int tid = threadIdx.x;
  const int bx = blockIdx.x, by = blockIdx.y, bz = blockIdx.z;

  for (int i = tid; i < 48 * 16; i += NTHREADS) wsm[i] = w[i];

  // haloed tile -> smem as half2 (one word = 2 adjacent channels)
  const int y0 = by * TY - 3, x0 = bx * TX - 3;
  for (int i = tid; i < TH * TW * NPR; i += NTHREADS) {
    int pr  = i & (NPR - 1);
    int pos = i >> 3;
    int py = pos / TW, px = pos - py * TW;
    int gy = y0 + py, gx = x0 + px;
    uint32_t v = 0u;  // half2(+0, +0)
    if ((unsigned)gy < (unsigned)Hn && (unsigned)gx < (unsigned)Wn) {
      const float2 f = *reinterpret_cast<const float2*>(
          &x[(((bz * Hn + gy) * Wn) + gx) * Cn + pr * 2]);
      v = h2u(__floats2half2_rn(f.x, f.y));
    }
    tile[i] = v;
  }
  __syncthreads();

  const int c2  = tid & (NPR - 1);   // channel pair
  const int pix = tid >> 3;          // 0..31
  {
    const int pxx = pix & (TX - 1);
    const int pyy = pix >> 3;
    const uint32_t* baseu = &tile[(((pyy + 3) * TW) + (pxx + 3)) * NPR + c2];
    const uint32_t tb = s2u(baseu);
    const uint32_t ab = s2u(&Ast[tid * NA]);

    __half2 V[49];
    // inner 3x3 -> slots 0..8
#pragma unroll
    for (int dy = -1; dy <= 1; dy++)
#pragma unroll
      for (int dx = -1; dx <= 1; dx++)
        V[(dy + 1) * 3 + (dx + 1)] = u2h(baseu[(dy * TW + dx) * NPR]);
    // 5x5 ring -> slots 9..24
    {
      int k = 9;
#pragma unroll
      for (int dy = -2; dy <= 2; dy++)
#pragma unroll
        for (int dx = -2; dx <= 2; dx++)
          if (dy < -1 || dy > 1 || dx < -1 || dx > 1) { V[k] = u2h(baseu[(dy * TW + dx) * NPR]); k++; }
    }

    // k=3: ascending index 6 of sorted 9
    S9::run(V);
    const __half2 m3 = V[Get<6, typename S9::type>::value];

    // k=5: ascending index 14 of sorted 25
    S16::run(V);
    M25::run(V);
    const __half2 m5 = V[Get<14, A25>::value];

    // stage sorted25 ranks 2..24 to smem, then load 7x7 ring late
    Stage<2>::run(V, ab);
    {
      int k = 25;
#pragma unroll
      for (int dy = -3; dy <= 3; dy++)
#pragma unroll
        for (int dx = -3; dx <= 3; dx++)
          if (dy < -2 || dy > 2 || dx < -2 || dx > 2) { V[k] = u2h(lds_u(tb + (dy * TW + dx) * (NPR * 4))); k++; }
    }

    S24::run(V);

    // k=7: rank 26 of union: m7 = max(A[2], B[1], max_{i=3..24} min(A[i], B[26-i]))
    __half2 acc0 = __hmax2(u2h(lds_u(ab + 0)), V[Get<1, B24>::value]);
    acc0 = __hmax2(acc0, Sel<4, 24>::run(V, ab));   // even i chain
    __half2 acc1 = Sel<3, 23>::run(V, ab);          // odd i chain
    const __half2 m7 = __hmax2(acc0, acc1);

    // concat order: [m7, m3, m5] -> float feat
    const float2 f7 = __half22float2(m7);
    const float2 f3 = __half22float2(m3);
    const float2 f5 = __half22float2(m5);
    float* fp = &feat[pix * 49];
    fp[     2 * c2] = f7.x;  fp[     2 * c2 + 1] = f7.y;
    fp[16 + 2 * c2] = f3.x;  fp[16 + 2 * c2 + 1] = f3.y;
    fp[32 + 2 * c2] = f5.x;  fp[32 + 2 * c2 + 1] = f5.y;
  }
  __syncthreads();

  // fused 1x1 conv (fp32): each thread computes 2 outputs for its pixel
  {
    const int o = c2 * 2;
    const float* f = &feat[pix * 49];
    float ax = 0.f, ay = 0.f;
#pragma unroll
    for (int cc = 0; cc < 48; cc++) {
      const float fv = f[cc];
      ax = fmaf(fv, wsm[cc * 16 + o], ax);
      ay = fmaf(fv, wsm[cc * 16 + o + 1], ay);
    }
    const int pxx = pix & (TX - 1), pyy = pix >> 3;
    const int gy = by * TY + pyy, gx = bx * TX + pxx;
    float2 r; r.x = ax; r.y = ay;
    *reinterpret_cast<float2*>(&out[(((bz * Hn + gy) * Wn) + gx) * Cn + o]) = r;
  }
}

extern "C" void kernel_launch(void* const* d_in, const int* in_sizes, int n_in,
                              void* d_out, int out_size) {
  const float* x = (const float*)d_in[0];
  const float* w = (const float*)d_in[1];
  float* out = (float*)d_out;
  dim3 grid(Wn / TX, Hn / TY, Bn);
  amblock_kernel<<<grid, NTHREADS>>>(x, w, out);
}

// round 6
// speedup vs baseline: 2.1693x; 1.1667x over previous
#include <cuda_runtime.h>
#include <cuda_fp16.h>
#include <cstdint>

#define DEVINL static __device__ __forceinline__

// ===================== compile-time int-list machinery =====================
template<int... Is> struct IL { static constexpr int size = sizeof...(Is); };

template<int H, typename L> struct Prepend;
template<int H, int... Is> struct Prepend<H, IL<Is...>> { using type = IL<H, Is...>; };

template<typename A, typename B> struct Concat;
template<int... As, int... Bs> struct Concat<IL<As...>, IL<Bs...>> { using type = IL<As..., Bs...>; };

template<int I, typename L> struct Get;
template<int H, int... T> struct Get<0, IL<H, T...>> { static constexpr int value = H; };
template<int I, int H, int... T> struct Get<I, IL<H, T...>> { static constexpr int value = Get<I-1, IL<T...>>::value; };

template<int N, typename L> struct Take;
template<> struct Take<0, IL<>> { using type = IL<>; };
template<int H, int... T> struct Take<0, IL<H, T...>> { using type = IL<>; };
template<int N, int H, int... T> struct Take<N, IL<H, T...>> {
  using type = typename Prepend<H, typename Take<N-1, IL<T...>>::type>::type;
};

template<int N, typename L> struct Drop;
template<> struct Drop<0, IL<>> { using type = IL<>; };
template<int H, int... T> struct Drop<0, IL<H, T...>> { using type = IL<H, T...>; };
template<int N, int H, int... T> struct Drop<N, IL<H, T...>> { using type = typename Drop<N-1, IL<T...>>::type; };

template<typename L> struct EvenOdd;
template<> struct EvenOdd<IL<>> { using even = IL<>; using odd = IL<>; };
template<int A> struct EvenOdd<IL<A>> { using even = IL<A>; using odd = IL<>; };
template<int A, int Bv, int... R> struct EvenOdd<IL<A, Bv, R...>> {
  using even = typename Prepend<A,  typename EvenOdd<IL<R...>>::even>::type;
  using odd  = typename Prepend<Bv, typename EvenOdd<IL<R...>>::odd >::type;
};

template<typename E, typename O> struct Interleave;
template<typename E> struct Interleave<E, IL<>> { using type = E; };
template<int E0, int... Es, int O0, int... Os>
struct Interleave<IL<E0, Es...>, IL<O0, Os...>> {
  using type = typename Concat<IL<E0, O0>, typename Interleave<IL<Es...>, IL<Os...>>::type>::type;
};

// ===================== packed f16x2 compare-exchange =====================
DEVINL void cas_(__half2& x, __half2& y) {
  __half2 lo = __hmin2(x, y);
  __half2 hi = __hmax2(x, y);
  x = lo; y = hi;
}

// cleanup step of odd-even merge: cas(O[i], E[i+1])
template<typename E, typename O> struct Cleanup {
  DEVINL void run(__half2*) {}
};
template<int E0, int E1, int... Es, int O0, int... Os>
struct Cleanup<IL<E0, E1, Es...>, IL<O0, Os...>> {
  DEVINL void run(__half2* v) {
    cas_(v[O0], v[E1]);
    Cleanup<IL<E1, Es...>, IL<Os...>>::run(v);
  }
};

// ===================== generalized Batcher odd-even merge =====================
template<typename A, typename B, int M = A::size, int N = B::size>
struct Merge {
  using ME = Merge<typename EvenOdd<A>::even, typename EvenOdd<B>::even>;
  using MO = Merge<typename EvenOdd<A>::odd,  typename EvenOdd<B>::odd >;
  using E = typename ME::type;
  using O = typename MO::type;
  using type = typename Interleave<E, O>::type;
  DEVINL void run(__half2* v) { ME::run(v); MO::run(v); Cleanup<E, O>::run(v); }
};
template<typename A, typename B, int N> struct Merge<A, B, 0, N> { using type = B; DEVINL void run(__half2*) {} };
template<typename A, typename B, int M> struct Merge<A, B, M, 0> { using type = A; DEVINL void run(__half2*) {} };
template<typename A, typename B>        struct Merge<A, B, 0, 0> { using type = IL<>; DEVINL void run(__half2*) {} };
template<typename A, typename B> struct Merge<A, B, 1, 1> {
  static constexpr int a0 = Get<0, A>::value;
  static constexpr int b0 = Get<0, B>::value;
  using type = IL<a0, b0>;
  DEVINL void run(__half2* v) { cas_(v[a0], v[b0]); }
};

// odd-even merge sort
template<typename L, int N = L::size>
struct Sort {
  static constexpr int Half = N / 2;
  using SA = Sort<typename Take<Half, L>::type>;
  using SB = Sort<typename Drop<Half, L>::type>;
  using MG = Merge<typename SA::type, typename SB::type>;
  using type = typename MG::type;
  DEVINL void run(__half2* v) { SA::run(v); SB::run(v); MG::run(v); }
};
template<typename L> struct Sort<L, 0> { using type = IL<>; DEVINL void run(__half2*) {} };
template<typename L> struct Sort<L, 1> { using type = L;    DEVINL void run(__half2*) {} };

template<int S, int N> struct Range {
  using type = typename Prepend<S, typename Range<S+1, N-1>::type>::type;
};
template<int S> struct Range<S, 0> { using type = IL<>; };

// ===================== opaque smem ld/st + bit casts =====================
DEVINL uint32_t s2u(const void* p) { return (uint32_t)__cvta_generic_to_shared(p); }
DEVINL void sts_u(uint32_t a, uint32_t v) {
  asm volatile("st.shared.b32 [%0], %1;" :: "r"(a), "r"(v) : "memory");
}
DEVINL uint32_t lds_u(uint32_t a) {
  uint32_t v;
  asm volatile("ld.shared.b32 %0, [%1];" : "=r"(v) : "r"(a) : "memory");
  return v;
}
DEVINL uint32_t h2u(__half2 h) { return *reinterpret_cast<uint32_t*>(&h); }
DEVINL __half2 u2h(uint32_t u) { return *reinterpret_cast<__half2*>(&u); }

// ===================== problem constants =====================
constexpr int Bn = 4, Hn = 256, Wn = 256, Cn = 16;
constexpr int TX = 8, TY = 4;              // output pixels per block: 32
constexpr int TW = TX + 6, TH = TY + 6;    // 14 x 10 haloed tile
constexpr int NPIX = TX * TY;              // 32
constexpr int NPR  = Cn / 2;               // 8 channel-pairs
constexpr int NTHREADS = NPIX * NPR;       // 256
constexpr int NA = 23;                     // staged ranks of sorted25: A[2..24]
constexpr int FS = 52;                     // feat / wsmT row stride (16B-aligned)

// Slot layout of V: 0..8 inner 3x3, 9..24 ring of 5x5, 25..48 ring of 7x7
using L9  = Range<0, 9>::type;
using L16 = Range<9, 16>::type;
using L24 = Range<25, 24>::type;
using S9  = Sort<L9>;
using S16 = Sort<L16>;
using S24 = Sort<L24>;
using M25 = Merge<typename S9::type, typename S16::type>;
using A25 = typename M25::type;
using B24 = typename S24::type;

// Stage sorted25 ranks R..24 to smem (opaque stores kill register liveness)
template<int R> struct Stage {
  DEVINL void run(const __half2* v, uint32_t ab) {
    sts_u(ab + (R - 2) * 4, h2u(v[Get<R, A25>::value]));
    Stage<R + 1>::run(v, ab);
  }
};
template<> struct Stage<25> { DEVINL void run(const __half2*, uint32_t) {} };

// Selection fold over terms t_i = min(a[i-OFS], B24[26-i]) for i = I, I+2, ...
// a[] is a register array preloaded from the staging buffer (compile-time idx).
template<int I, int IEnd, int OFS> struct SelA {
  DEVINL __half2 run(const __half2* v, const __half2* a) {
    __half2 t = __hmin2(a[I - OFS], v[Get<26 - I, B24>::value]);
    return __hmax2(t, SelA<I + 2, IEnd, OFS>::run(v, a));
  }
};
template<int IEnd, int OFS> struct SelA<IEnd, IEnd, OFS> {
  DEVINL __half2 run(const __half2* v, const __half2* a) {
    return __hmin2(a[IEnd - OFS], v[Get<26 - IEnd, B24>::value]);
  }
};

__global__ void __launch_bounds__(NTHREADS, 6)
amblock_kernel(const float* __restrict__ x, const float* __restrict__ w,
               float* __restrict__ out) {
  // tile (4480B) and feat (6656B) have disjoint lifetimes -> union
  __shared__ __align__(16) char upool[NPIX * FS * 4];      // 6656B
  __shared__ __align__(16) float wsmT[16 * FS];            // transposed weights
  __shared__ uint32_t Ast[NTHREADS * NA];                  // 23KB staging

  uint32_t* tile = reinterpret_cast<uint32_t*>(upool);     // [TH][TW][NPR]
  float*    feat = reinterpret_cast<float*>(upool);        // [NPIX][FS]

  const int tid = threadIdx.x;
  const int bx = blockIdx.x, by = blockIdx.y, bz = blockIdx.z;

  // transposed weights: wsmT[o*FS + cc] = w[cc*16 + o]
  for (int i = tid; i < 16 * 48; i += NTHREADS) {
    int o = i & 15, cc = i >> 4;
    wsmT[o * FS + cc] = w[cc * 16 + o];
  }

  // haloed tile -> smem as half2 (one word = 2 adjacent channels)
  const int y0 = by * TY - 3, x0 = bx * TX - 3;
  for (int i = tid; i < TH * TW * NPR; i += NTHREADS) {
    int pr  = i & (NPR - 1);
    int pos = i >> 3;
    int py = pos / TW, px = pos - py * TW;
    int gy = y0 + py, gx = x0 + px;
    uint32_t v = 0u;
    if ((unsigned)gy < (unsigned)Hn && (unsigned)gx < (unsigned)Wn) {
      const float2 f = *reinterpret_cast<const float2*>(
          &x[(((bz * Hn + gy) * Wn) + gx) * Cn + pr * 2]);
      v = h2u(__floats2half2_rn(f.x, f.y));
    }
    tile[i] = v;
  }
  __syncthreads();

  const int c2  = tid & (NPR - 1);   // channel pair
  const int pix = tid >> 3;          // 0..31
  __half2 m7, m3, m5;
  {
    const int pxx = pix & (TX - 1);
    const int pyy = pix >> 3;
    const uint32_t* baseu = &tile[(((pyy + 3) * TW) + (pxx + 3)) * NPR + c2];
    const uint32_t tb = s2u(baseu);
    const uint32_t ab = s2u(&Ast[tid * NA]);

    __half2 V[49];
    // inner 3x3 -> slots 0..8
#pragma unroll
    for (int dy = -1; dy <= 1; dy++)
#pragma unroll
      for (int dx = -1; dx <= 1; dx++)
        V[(dy + 1) * 3 + (dx + 1)] = u2h(baseu[(dy * TW + dx) * NPR]);
    // 5x5 ring -> slots 9..24
    {
      int k = 9;
#pragma unroll
      for (int dy = -2; dy <= 2; dy++)
#pragma unroll
        for (int dx = -2; dx <= 2; dx++)
          if (dy < -1 || dy > 1 || dx < -1 || dx > 1) { V[k] = u2h(baseu[(dy * TW + dx) * NPR]); k++; }
    }

    // k=3: ascending index 6 of sorted 9
    S9::run(V);
    m3 = V[Get<6, typename S9::type>::value];

    // k=5: ascending index 14 of sorted 25
    S16::run(V);
    M25::run(V);
    m5 = V[Get<14, A25>::value];

    // stage sorted25 ranks 2..24 to smem, then load 7x7 ring late
    Stage<2>::run(V, ab);
    {
      int k = 25;
#pragma unroll
      for (int dy = -3; dy <= 3; dy++)
#pragma unroll
        for (int dx = -3; dx <= 3; dx++)
          if (dy < -2 || dy > 2 || dx < -2 || dx > 2) { V[k] = u2h(lds_u(tb + (dy * TW + dx) * (NPR * 4))); k++; }
    }

    S24::run(V);

    // k=7: rank 26 of union: m7 = max(A[2], B[1], max_{i=3..24} min(A[i], B[26-i]))
    // Batched reloads: two groups of 11 A-values in registers (MLP), then
    // step-2 max-chains (short dependency depth).
    {
      __half2 a[11];
#pragma unroll
      for (int r = 0; r < 11; r++) a[r] = u2h(lds_u(ab + (1 + r) * 4));  // A[3..13] -> a[0..10]
      __half2 acc = __hmax2(u2h(lds_u(ab + 0)), V[Get<1, B24>::value]);  // A[2], B[1]
      acc = __hmax2(acc, SelA<3, 13, 3>::run(V, a));    // i = 3,5,..,13
      acc = __hmax2(acc, SelA<4, 12, 3>::run(V, a));    // i = 4,6,..,12
#pragma unroll
      for (int r = 0; r < 11; r++) a[r] = u2h(lds_u(ab + (12 + r) * 4)); // A[14..24] -> a[0..10]
      acc = __hmax2(acc, SelA<14, 24, 14>::run(V, a));  // i = 14,..,24
      acc = __hmax2(acc, SelA<15, 23, 14>::run(V, a));  // i = 15,..,23
      m7 = acc;
    }
  }

  // tile is dead; feat overlays it. Barrier before reuse.
  __syncthreads();
  {
    const float2 f7 = __half22float2(m7);
    const float2 f3 = __half22float2(m3);
    const float2 f5 = __half22float2(m5);
    float* fp = &feat[pix * FS];
    fp[     2 * c2] = f7.x;  fp[     2 * c2 + 1] = f7.y;
    fp[16 + 2 * c2] = f3.x;  fp[16 + 2 * c2 + 1] = f3.y;
    fp[32 + 2 * c2] = f5.x;  fp[32 + 2 * c2 + 1] = f5.y;
  }
  __syncthreads();

  // fused 1x1 conv (fp32): thread computes output channel o for 2 pixels
  {
    const int o  = tid & 15;
    const int p0 = tid >> 4;                 // pixels p0 and p0+16
    const float4* wrow = reinterpret_cast<const float4*>(&wsmT[o * FS]);
    const float4* f0   = reinterpret_cast<const float4*>(&feat[p0 * FS]);
    const float4* f1   = reinterpret_cast<const float4*>(&feat[(p0 + 16) * FS]);
    float acc0 = 0.f, acc1 = 0.f;
#pragma unroll
    for (int q = 0; q < 12; q++) {
      const float4 wv = wrow[q];
      const float4 av = f0[q];
      const float4 bv = f1[q];
      acc0 = fmaf(av.x, wv.x, acc0); acc1 = fmaf(bv.x, wv.x, acc1);
      acc0 = fmaf(av.y, wv.y, acc0); acc1 = fmaf(bv.y, wv.y, acc1);
      acc0 = fmaf(av.z, wv.z, acc0); acc1 = fmaf(bv.z, wv.z, acc1);
      acc0 = fmaf(av.w, wv.w, acc0); acc1 = fmaf(bv.w, wv.w, acc1);
    }
    const int px0 = p0 & (TX - 1), py0 = p0 >> 3;
    const int px1 = (p0 + 16) & (TX - 1), py1 = (p0 + 16) >> 3;
    out[(((bz * Hn + by * TY + py0) * Wn) + bx * TX + px0) * Cn + o] = acc0;
    out[(((bz * Hn + by * TY + py1) * Wn) + bx * TX + px1) * Cn + o] = acc1;
  }
}

extern "C" void kernel_launch(void* const* d_in, const int* in_sizes, int n_in,
                              void* d_out, int out_size) {
  const float* x = (const float*)d_in[0];
  const float* w = (const float*)d_in[1];
  float* out = (float*)d_out;
  dim3 grid(Wn / TX, Hn / TY, Bn);
  amblock_kernel<<<grid, NTHREADS>>>(x, w, out);
}